// round 7
// baseline (speedup 1.0000x reference)
#include <cuda_runtime.h>
#include <cuda_bf16.h>
#include <cstdint>

#define NB 32
#define NN 400
#define NC 720
#define NH 12
#define HD 60
#define BH (NB * NH)
#define SCALE 0.1290994448735806f   // 60^-0.5

// tcgen05 is only legal in an arch-accelerated (compute_103a) compile pass.
#if defined(__CUDA_ARCH__) && (__CUDA_ARCH__ >= 1000) && \
    (defined(__CUDA_ARCH_FEAT_SM103_ALL) || defined(__CUDA_ARCH_FEAT_SM100_ALL))
#define HAS_TC 1
#else
#define HAS_TC 0
#endif

// fp32 q/k for the fallback path
__device__ float g_q[NB * NH * NN * HD];
__device__ float g_k[NB * NH * NN * HD];
// bf16 hi/lo split, K padded 60 -> 64 (128B rows = one SW128 atom) for tcgen05.
// Pad cols / tail rows are zero-initialized globals, never written -> stay 0.
#define KP 64
#define QK_ROWS (BH * NN + 128)
__device__ __nv_bfloat16 g_qh[QK_ROWS * KP];
__device__ __nv_bfloat16 g_ql[QK_ROWS * KP];
__device__ __nv_bfloat16 g_kh[QK_ROWS * KP];
__device__ __nv_bfloat16 g_kl[QK_ROWS * KP];
__device__ int g_roi[NB * NN];
__device__ int g_use_tc;

// ---------------------------------------------------------------------------
// Dispatch flag: 1 iff the selected cubin was compiled with sm_103a features.
// ---------------------------------------------------------------------------
__global__ void set_flag_kernel() {
#if HAS_TC
    g_use_tc = 1;
#else
    g_use_tc = 0;
#endif
}

// ---------------------------------------------------------------------------
// PTX helpers
// ---------------------------------------------------------------------------
__device__ __forceinline__ uint32_t smem_u32(const void* p) {
    uint32_t a;
    asm("{ .reg .u64 t; cvta.to.shared.u64 t, %1; cvt.u32.u64 %0, t; }"
        : "=r"(a) : "l"(p));
    return a;
}

#if HAS_TC
__device__ __forceinline__ uint32_t elect_one() {
    uint32_t pred;
    asm volatile("{ .reg .pred p; elect.sync _|p, 0xFFFFFFFF; selp.b32 %0, 1, 0, p; }"
                 : "=r"(pred));
    return pred;
}
#define TC_ALLOC(smem_addr, ncols) \
    asm volatile("tcgen05.alloc.cta_group::1.sync.aligned.shared::cta.b32 [%0], %1;" \
                 :: "r"(smem_addr), "r"(ncols) : "memory")
#define TC_RELINQ() \
    asm volatile("tcgen05.relinquish_alloc_permit.cta_group::1.sync.aligned;")
#define TC_DEALLOC(tmem, ncols) \
    asm volatile("tcgen05.dealloc.cta_group::1.sync.aligned.b32 %0, %1;" \
                 :: "r"(tmem), "r"(ncols))
#define TC_COMMIT(mbar) \
    asm volatile("tcgen05.commit.cta_group::1.mbarrier::arrive::one.shared::cluster.b64 [%0];" \
                 :: "r"(mbar) : "memory")
#define TC_FENCE_AFTER() \
    asm volatile("tcgen05.fence::after_thread_sync;" ::: "memory")
#define TC_WAIT_LD() \
    asm volatile("tcgen05.wait::ld.sync.aligned;" ::: "memory")
#define MBAR_INIT(mbar, cnt) \
    asm volatile("mbarrier.init.shared.b64 [%0], %1;" :: "r"(mbar), "r"(cnt) : "memory")
#define MBAR_WAIT(mbar, parity) do {                                          \
    asm volatile(                                                             \
        "{\n\t.reg .pred P1;\n\t"                                             \
        "WAIT_LOOP_%=:\n\t"                                                   \
        "mbarrier.try_wait.parity.acquire.cta.shared::cta.b64 P1, [%0], %1, 0x989680;\n\t" \
        "@P1 bra.uni WAIT_DONE_%=;\n\t"                                       \
        "bra.uni WAIT_LOOP_%=;\n\t"                                           \
        "WAIT_DONE_%=:\n\t}"                                                  \
        :: "r"(mbar), "r"(parity) : "memory");                                \
} while (0)

__device__ __forceinline__ void mma_f16_ss(uint32_t d_tmem, uint64_t a_desc,
                                           uint64_t b_desc, uint32_t idesc,
                                           uint32_t enable_d) {
    asm volatile(
        "{\n\t.reg .pred p;\n\t"
        "setp.ne.u32 p, %4, 0;\n\t"
        "tcgen05.mma.cta_group::1.kind::f16 [%0], %1, %2, %3, {%5, %5, %5, %5}, p;\n\t"
        "}"
        :: "r"(d_tmem), "l"(a_desc), "l"(b_desc), "r"(idesc), "r"(enable_d), "r"(0u)
        : "memory");
}

#define TC_LD_X32(r, addr) \
    asm volatile("tcgen05.ld.sync.aligned.32x32b.x32.b32 " \
        "{%0,%1,%2,%3,%4,%5,%6,%7,%8,%9,%10,%11,%12,%13,%14,%15," \
        "%16,%17,%18,%19,%20,%21,%22,%23,%24,%25,%26,%27,%28,%29,%30,%31}, [%32];" \
        : "=r"((r)[0]),"=r"((r)[1]),"=r"((r)[2]),"=r"((r)[3]), \
          "=r"((r)[4]),"=r"((r)[5]),"=r"((r)[6]),"=r"((r)[7]), \
          "=r"((r)[8]),"=r"((r)[9]),"=r"((r)[10]),"=r"((r)[11]), \
          "=r"((r)[12]),"=r"((r)[13]),"=r"((r)[14]),"=r"((r)[15]), \
          "=r"((r)[16]),"=r"((r)[17]),"=r"((r)[18]),"=r"((r)[19]), \
          "=r"((r)[20]),"=r"((r)[21]),"=r"((r)[22]),"=r"((r)[23]), \
          "=r"((r)[24]),"=r"((r)[25]),"=r"((r)[26]),"=r"((r)[27]), \
          "=r"((r)[28]),"=r"((r)[29]),"=r"((r)[30]),"=r"((r)[31]) \
        : "r"(addr))
#define TC_LD_X16(r, addr) \
    asm volatile("tcgen05.ld.sync.aligned.32x32b.x16.b32 " \
        "{%0,%1,%2,%3,%4,%5,%6,%7,%8,%9,%10,%11,%12,%13,%14,%15}, [%16];" \
        : "=r"((r)[0]),"=r"((r)[1]),"=r"((r)[2]),"=r"((r)[3]), \
          "=r"((r)[4]),"=r"((r)[5]),"=r"((r)[6]),"=r"((r)[7]), \
          "=r"((r)[8]),"=r"((r)[9]),"=r"((r)[10]),"=r"((r)[11]), \
          "=r"((r)[12]),"=r"((r)[13]),"=r"((r)[14]),"=r"((r)[15]) \
        : "r"(addr))

// SW128 K-major descriptor: layout=SW128, version=1 (Blackwell), SBO=64, LBO=1
static __device__ __forceinline__ uint64_t make_desc(uint32_t addr) {
    const uint64_t base = (uint64_t(2) << 61) | (uint64_t(1) << 46) |
                          (uint64_t(64) << 32) | (uint64_t(1) << 16);
    return base | ((uint64_t)(addr >> 4) & 0x3FFF);
}
#endif  // HAS_TC

#define SWZ(x) ((x) ^ (((x) >> 3) & 0x70))

// ---------------------------------------------------------------------------
// Kernel 1: roi_mask[b][n] = any_c mask[b][c][n] != 0   (mask is (B, C, N))
// ---------------------------------------------------------------------------
__global__ __launch_bounds__(128) void roi_kernel(const int* __restrict__ mask) {
    int b = blockIdx.y;
    int n = blockIdx.x * blockDim.x + threadIdx.x;
    if (n >= NN) return;
    const int* p = mask + (size_t)b * NC * NN + n;
    int s = 0;
    for (int c = 0; c < NC; ++c) s |= p[(size_t)c * NN];
    g_roi[b * NN + n] = s;
}

// ---------------------------------------------------------------------------
// Kernel 2: Q/K projection (fp32 SIMT). Epilogue writes BOTH fp32 q/k
// (fallback) and bf16 hi/lo split padded tiles (tcgen05 path). q pre-scaled.
// ---------------------------------------------------------------------------
__global__ __launch_bounds__(256) void qk_proj(const float* __restrict__ x,
                                               const float* __restrict__ w) {
    __shared__ float As[16][64];
    __shared__ float Ws[16][64];
    int tid = threadIdx.x;
    int row0 = blockIdx.y * 64;
    int col0 = blockIdx.x * 64;
    int lr = tid >> 2;
    int lk = (tid & 3) << 2;
    int ty = tid >> 4, tx = tid & 15;
    float acc[4][4] = {};

    for (int kk = 0; kk < NC; kk += 16) {
        float4 av = *(const float4*)(x + (size_t)(row0 + lr) * NC + kk + lk);
        float4 wv = make_float4(0.f, 0.f, 0.f, 0.f);
        int jr = col0 + lr;
        if (jr < 2 * NC) wv = *(const float4*)(w + (size_t)jr * NC + kk + lk);
        As[lk + 0][lr] = av.x; As[lk + 1][lr] = av.y;
        As[lk + 2][lr] = av.z; As[lk + 3][lr] = av.w;
        Ws[lk + 0][lr] = wv.x; Ws[lk + 1][lr] = wv.y;
        Ws[lk + 2][lr] = wv.z; Ws[lk + 3][lr] = wv.w;
        __syncthreads();
#pragma unroll
        for (int k = 0; k < 16; ++k) {
            float4 a = *(const float4*)&As[k][ty * 4];
            float4 b = *(const float4*)&Ws[k][tx * 4];
            float aa[4] = {a.x, a.y, a.z, a.w};
            float bb[4] = {b.x, b.y, b.z, b.w};
#pragma unroll
            for (int i = 0; i < 4; ++i)
#pragma unroll
                for (int j = 0; j < 4; ++j) acc[i][j] += aa[i] * bb[j];
        }
        __syncthreads();
    }

#pragma unroll
    for (int i = 0; i < 4; ++i) {
        int gi = row0 + ty * 4 + i;           // global x-row (b*400+n)
        int b = gi / NN, n = gi - b * NN;
#pragma unroll
        for (int j = 0; j < 4; ++j) {
            int jc = col0 + tx * 4 + j;
            if (jc < 2 * NC) {
                int t = jc / NC;
                int r = jc - t * NC;
                int h = r / HD, e = r - h * HD;
                size_t offf = ((size_t)(b * NH + h) * NN + n) * HD + e;
                size_t offp = ((size_t)(b * NH + h) * NN + n) * KP + e;
                float v = acc[i][j];
                if (t == 0) v *= SCALE;
                __nv_bfloat16 hi = __float2bfloat16(v);
                __nv_bfloat16 lo = __float2bfloat16(v - __bfloat162float(hi));
                if (t == 0) {
                    g_q[offf] = v;
                    g_qh[offp] = hi; g_ql[offp] = lo;
                } else {
                    g_k[offf] = v;
                    g_kh[offp] = hi; g_kl[offp] = lo;
                }
            }
        }
    }
}

// ---------------------------------------------------------------------------
// Kernel 3 (tcgen05 path): fused attention. S = Qh*Kh^T + Qh*Kl^T + Ql*Kh^T
// (fp32 TMEM accum), per-lane masked softmax from TMEM, transposed store.
// One CTA = one (b,h) x 128-row tile. 128 threads. Empty body if !HAS_TC.
// ---------------------------------------------------------------------------
#define OFF_TMEM 0
#define OFF_MBAR 8
#define OFF_ROI  16
#define OFF_QH   2048
#define OFF_QL   (OFF_QH + 16384)
#define OFF_KH   (OFF_QL + 16384)
#define OFF_KL   (OFF_KH + 51200)
#define SMEM_TOTAL (OFF_KL + 51200)   // 137216 B

#define IDESC(Nv) ((1u << 4) | (1u << 7) | (1u << 10) | (((Nv) / 8u) << 17) | (8u << 24))

__global__ __launch_bounds__(128) void attn_tc_kernel(float* __restrict__ out) {
#if HAS_TC
    extern __shared__ char smem[];
    uint32_t sb = smem_u32(smem);
    int tid = threadIdx.x;
    int wid = tid >> 5, lid = tid & 31;
    int mtile = blockIdx.x;            // 0..3
    int bh = blockIdx.y;               // 0..383
    int b = bh / NH;
    int row0 = mtile * 128;

    if (wid == 0) {
        TC_ALLOC(sb + OFF_TMEM, 512);
        TC_RELINQ();
    }
    __syncthreads();
    uint32_t tmem;
    asm volatile("ld.shared.b32 %0, [%1];" : "=r"(tmem) : "r"(sb + OFF_TMEM));

    int* roi_s = (int*)(smem + OFF_ROI);
    for (int m = tid; m < NN; m += 128) roi_s[m] = g_roi[b * NN + m];

    // Q tiles: 128 rows x 128B (hi, lo), SW128 swizzle
    {
        const char* srcH = (const char*)g_qh + ((size_t)(bh * NN + row0)) * 128;
        const char* srcL = (const char*)g_ql + ((size_t)(bh * NN + row0)) * 128;
        for (int i = tid; i < 128 * 8; i += 128) {
            uint32_t bo = (uint32_t)i * 16;
            uint32_t sw = SWZ(bo);
            *(float4*)(smem + OFF_QH + sw) = *(const float4*)(srcH + bo);
            *(float4*)(smem + OFF_QL + sw) = *(const float4*)(srcL + bo);
        }
    }
    // K tiles: all 400 rows x 128B (hi, lo)
    {
        const char* srcH = (const char*)g_kh + ((size_t)bh * NN) * 128;
        const char* srcL = (const char*)g_kl + ((size_t)bh * NN) * 128;
        for (int i = tid; i < NN * 8; i += 128) {
            uint32_t bo = (uint32_t)i * 16;
            uint32_t sw = SWZ(bo);
            *(float4*)(smem + OFF_KH + sw) = *(const float4*)(srcH + bo);
            *(float4*)(smem + OFF_KL + sw) = *(const float4*)(srcL + bo);
        }
    }
    __syncthreads();

    if (wid == 0) {
        if (elect_one()) MBAR_INIT(sb + OFF_MBAR, 1);
        asm volatile("fence.proxy.async.shared::cta;" ::: "memory");
        if (elect_one()) {
            uint64_t dqh = make_desc(sb + OFF_QH);
            uint64_t dql = make_desc(sb + OFF_QL);
            uint64_t dkh = make_desc(sb + OFF_KH);
            uint64_t dkl = make_desc(sb + OFF_KL);
            const uint32_t idesc128 = IDESC(128);
            const uint32_t idesc16  = IDESC(16);
#pragma unroll
            for (int split = 0; split < 3; ++split) {
                uint64_t da = (split == 2) ? dql : dqh;
                uint64_t db = (split == 1) ? dkl : dkh;
#pragma unroll
                for (int k = 0; k < 4; ++k) {          // K=64 -> 4 x K16
                    uint32_t en = (split > 0 || k > 0) ? 1u : 0u;
#pragma unroll
                    for (int c = 0; c < 4; ++c) {      // N chunks 128,128,128,16
                        mma_f16_ss(tmem + c * 128,
                                   da + k * 2,
                                   db + (uint64_t)c * 1024 + k * 2,
                                   (c == 3) ? idesc16 : idesc128, en);
                    }
                }
            }
            TC_COMMIT(sb + OFF_MBAR);
        }
    }
    __syncthreads();
    MBAR_WAIT(sb + OFF_MBAR, 0);
    TC_FENCE_AFTER();

    // fused masked softmax: each lane owns one logits row in its TMEM lane
    uint32_t vals[32];
    float sum = 0.f;
    for (int c0 = 0; c0 < NN; c0 += 32) {
        int w = NN - c0;
        if (w >= 32) { TC_LD_X32(vals, tmem + c0); w = 32; }
        else         { TC_LD_X16(vals, tmem + c0); }
        TC_WAIT_LD();
        for (int j = 0; j < w; ++j) {
            float e = roi_s[c0 + j] ? __expf(__uint_as_float(vals[j])) : 0.f;
            sum += e;
        }
    }
    float inv = (sum > 0.f) ? 1.f / sum : 0.f;

    // pass 2: recompute, transpose through smem (reuse dead Q region), store
    float* tileS = (float*)(smem + OFF_QH) + wid * (32 * 33);
    float* ob = out + (size_t)bh * NN * NN;
    int rbase = row0 + wid * 32;
    for (int c0 = 0; c0 < NN; c0 += 32) {
        int w = NN - c0;
        if (w >= 32) { TC_LD_X32(vals, tmem + c0); w = 32; }
        else         { TC_LD_X16(vals, tmem + c0); }
        TC_WAIT_LD();
        for (int j = 0; j < w; ++j) {
            float e = roi_s[c0 + j] ? __expf(__uint_as_float(vals[j])) : 0.f;
            tileS[lid * 33 + j] = e * inv;
        }
        __syncwarp();
        for (int r = 0; r < 32; ++r) {
            int n = rbase + r;
            if (n < NN && lid < w)
                ob[(size_t)n * NN + c0 + lid] = tileS[r * 33 + lid];
        }
        __syncwarp();
    }

    __syncthreads();
    if (wid == 0) TC_DEALLOC(tmem, 512);
#else
    (void)out;   // compute_103 pass: no-op; fallback kernels do the work
#endif
}

// ---------------------------------------------------------------------------
// Fallback kernel A: fp32 masked logits -> d_out (skipped when g_use_tc).
// ---------------------------------------------------------------------------
__global__ __launch_bounds__(256) void logits_fb_kernel(float* __restrict__ out) {
    if (g_use_tc) return;
    __shared__ float qs[HD][64];
    __shared__ float ks[HD][64];
    int bh = blockIdx.z;
    int n0 = blockIdx.y * 64;
    int m0 = blockIdx.x * 64;
    const float* qb = g_q + (size_t)bh * NN * HD;
    const float* kb = g_k + (size_t)bh * NN * HD;
    int tid = threadIdx.x;

    for (int idx = tid; idx < 64 * HD; idx += 256) {
        int r = idx / HD, e = idx - r * HD;
        int n = n0 + r;
        qs[e][r] = (n < NN) ? qb[(size_t)n * HD + e] : 0.f;
        int m = m0 + r;
        ks[e][r] = (m < NN) ? kb[(size_t)m * HD + e] : 0.f;
    }
    __syncthreads();

    int ty = tid >> 4, tx = tid & 15;
    float acc[4][4] = {};
#pragma unroll
    for (int e = 0; e < HD; ++e) {
        float4 a = *(const float4*)&qs[e][ty * 4];
        float4 b = *(const float4*)&ks[e][tx * 4];
        float aa[4] = {a.x, a.y, a.z, a.w};
        float bb[4] = {b.x, b.y, b.z, b.w};
#pragma unroll
        for (int i = 0; i < 4; ++i)
#pragma unroll
            for (int j = 0; j < 4; ++j) acc[i][j] += aa[i] * bb[j];
    }

    int b = bh / NH;
    const int* roi = g_roi + b * NN;
    float* ob = out + (size_t)bh * NN * NN;
#pragma unroll
    for (int i = 0; i < 4; ++i) {
        int n = n0 + ty * 4 + i;
        if (n < NN) {
#pragma unroll
            for (int j = 0; j < 4; ++j) {
                int m = m0 + tx * 4 + j;
                if (m < NN)
                    ob[(size_t)n * NN + m] = roi[m] ? acc[i][j] : -10000.0f;
            }
        }
    }
}

// ---------------------------------------------------------------------------
// Fallback kernel B: in-place softmax over last dim (skipped when g_use_tc).
// ---------------------------------------------------------------------------
__global__ __launch_bounds__(128) void softmax_fb_kernel(float* __restrict__ out) {
    if (g_use_tc) return;
    size_t row = blockIdx.x;
    float* p = out + row * (size_t)NN;
    int t = threadIdx.x;
    __shared__ float rm[4], rs[4];

    float v[4];
    float mx = -3.0e38f;
#pragma unroll
    for (int i = 0; i < 4; ++i) {
        int idx = t + i * 128;
        v[i] = (idx < NN) ? p[idx] : -3.0e38f;
        mx = fmaxf(mx, v[i]);
    }
#pragma unroll
    for (int o = 16; o; o >>= 1) mx = fmaxf(mx, __shfl_xor_sync(0xffffffffu, mx, o));
    if ((t & 31) == 0) rm[t >> 5] = mx;
    __syncthreads();
    mx = fmaxf(fmaxf(rm[0], rm[1]), fmaxf(rm[2], rm[3]));

    float s = 0.f;
#pragma unroll
    for (int i = 0; i < 4; ++i) {
        float e = __expf(v[i] - mx);
        v[i] = e;
        int idx = t + i * 128;
        if (idx < NN) s += e;
    }
#pragma unroll
    for (int o = 16; o; o >>= 1) s += __shfl_xor_sync(0xffffffffu, s, o);
    if ((t & 31) == 0) rs[t >> 5] = s;
    __syncthreads();
    s = rs[0] + rs[1] + rs[2] + rs[3];
    float inv = 1.0f / s;
#pragma unroll
    for (int i = 0; i < 4; ++i) {
        int idx = t + i * 128;
        if (idx < NN) p[idx] = v[i] * inv;
    }
}

// ---------------------------------------------------------------------------
extern "C" void kernel_launch(void* const* d_in, const int* in_sizes, int n_in,
                              void* d_out, int out_size) {
    const float* x    = (const float*)d_in[0];   // (32, 400, 720) fp32
    const int*   mask = (const int*)d_in[1];     // (32, 720, 400) int32
    const float* w    = (const float*)d_in[2];   // (2160, 720) fp32
    float* out = (float*)d_out;                  // (32, 12, 400, 400) fp32

    static bool attr_done = false;
    if (!attr_done) {
        cudaFuncSetAttribute(attn_tc_kernel,
                             cudaFuncAttributeMaxDynamicSharedMemorySize,
                             SMEM_TOTAL);
        attr_done = true;
    }

    set_flag_kernel<<<1, 1>>>();
    roi_kernel<<<dim3((NN + 127) / 128, NB), 128>>>(mask);
    qk_proj<<<dim3((2 * NC + 63) / 64, (NB * NN) / 64), 256>>>(x, w);
    attn_tc_kernel<<<dim3(4, BH), 128, SMEM_TOTAL>>>(out);
    logits_fb_kernel<<<dim3((NN + 63) / 64, (NN + 63) / 64, BH), 256>>>(out);
    softmax_fb_kernel<<<BH * NN, 128>>>(out);
}